// round 7
// baseline (speedup 1.0000x reference)
#include <cuda_runtime.h>
#include <math.h>

// Problem constants
#define NB 4          // batch
#define NM 32         // masks (sam_masks[:,1:])
#define C2 1024       // channels of layer 2
#define P2 1024       // 32*32 pixels of layer 2
#define HMASK 512     // sam mask resolution
#define KS 32         // K-splits for q GEMM
#define KC 32         // K per split (KS*KC = 1024)
#define NR 128        // NB*NM rows in q GEMM

// Output layout: out0 | out1 | out2 concatenated (floats)
#define OFF1 16777216L   // 4*256*128*128
#define OFF2 25165824L   // OFF1 + 4*512*64*64
#define TOT  29360128L   // OFF2 + 4*1024*32*32

// Copy region = out0|out1 = OFF2 floats = 6291456 float4, sliced across the
// chain kernels as extra blocks (fills idle SMs, overlaps the serial chain).
// starts (in float4) and block counts; per-block float4 = blockDim*4.
#define CPN_IDX 300   // 1024-thr blocks -> 4096 f4 each
#define CPS_IDX 0L
#define CPN_MFP 600   // 256-thr blocks -> 1024 f4 each
#define CPS_MFP 1228800L
#define CPN_MF0 1000
#define CPS_MF0 1843200L
#define CPN_QG  400
#define CPS_QG  2867200L
#define CPN_QR  1000
#define CPS_QR  3276800L
#define CPN_SE  990
#define CPS_SE  4300800L
#define CPN_GP  600
#define CPS_GP  5314560L
#define CPN_SC  354
#define CPS_SC  5928960L
// 300*4096 + (600+1000+400+1000+990+600+354)*1024 = 6291456 = OFF2/4  ✓

// -------- scratch (device globals; no allocation allowed) --------
__device__ int   g_idx[NB*P2];           // mask id per sampled pixel, -1 if none
__device__ float g_mfpart[NB*4*NM*C2];   // pooling partials over 4 pixel-chunks
__device__ float g_mf0[NR*C2];           // normalized mask features (row-major)
__device__ float g_qpart[KS*NR*C2];      // q GEMM K-split partials (16MB)
__device__ float g_q[NR*C2];             // q = mf0 @ W^T + b
__device__ float g_qn[NR];               // ||q_m||
__device__ float g_edge[NB*NM*NM];       // edge weights
__device__ float g_gp[NR*C2];            // graph-attn output (unnormalized)
__device__ float g_gpsqp[NB*4*NM];       // per-ct-block partial sq-norms of gp
__device__ float g_scale[NR];            // sigmoid(g)/max(||gp_m||,1e-12)

// Copy slice: each block moves blockDim*4 float4 of out0|out1.
__device__ __forceinline__ void copy_chunk(const float* __restrict__ f0,
                                           const float* __restrict__ f1,
                                           float* __restrict__ out, long base4) {
    long i4 = base4 + threadIdx.x;
    #pragma unroll
    for (int j = 0; j < 4; j++, i4 += blockDim.x) {
        float4 v = (i4 < OFF1/4) ? ((const float4*)f0)[i4]
                                 : ((const float4*)f1)[i4 - OFF1/4];
        ((float4*)out)[i4] = v;
    }
}

// -------- K1: argmax mask id; own 128 blocks (b,row) + copy tail --------
__global__ void k_idx(const int* __restrict__ sam, const float* __restrict__ f0,
                      const float* __restrict__ f1, float* __restrict__ out) {
    int bid = blockIdx.x;
    if (bid >= 128) { copy_chunk(f0, f1, out, CPS_IDX + (long)(bid-128)*4096); return; }
    int b = bid >> 5, y = bid & 31;
    int t = threadIdx.x;                     // 1024: m = t>>5, x = t&31
    int m = t >> 5, x = t & 31;
    __shared__ int best[32];
    if (t < 32) best[t] = -1;
    __syncthreads();
    long off = ((long)b*33 + (m+1))*HMASK*HMASK + (long)(y*16)*HMASK + (long)(x*16);
    if (__ldg(sam + off) == 1) atomicMax(&best[x], m);   // int: deterministic
    __syncthreads();
    if (t < 32) g_idx[b*P2 + y*32 + t] = best[t];
}

// -------- K2: segmented pooling, per-thread private smem bins + copy tail --------
__global__ void k_mfpart(const float* __restrict__ feat2, const float* __restrict__ f0,
                         const float* __restrict__ f1, float* __restrict__ out) {
    int bid = blockIdx.x;
    if (bid >= 64) { copy_chunk(f0, f1, out, CPS_MFP + (long)(bid-64)*1024); return; }
    int b = bid >> 4, ct = (bid >> 2) & 3, pc = bid & 3;
    int t = threadIdx.x;                 // 256, thread = one channel
    int c = ct*256 + t;
    __shared__ float sbins[NM*256];      // [m*256+t]: bank = t%32, conflict-free
    __shared__ int   sidx[256];
    #pragma unroll
    for (int m = 0; m < NM; m++) sbins[m*256 + t] = 0.f;
    sidx[t] = g_idx[b*P2 + pc*256 + t];
    __syncthreads();
    const float4* fp = (const float4*)(feat2 + ((long)b*C2 + c)*P2 + pc*256);
    #pragma unroll 4
    for (int i = 0; i < 64; i++) {
        float4 v = fp[i];
        int p0 = i*4;
        int m0 = sidx[p0+0], m1 = sidx[p0+1], m2 = sidx[p0+2], m3 = sidx[p0+3];
        if (m0 >= 0) sbins[m0*256 + t] += v.x;
        if (m1 >= 0) sbins[m1*256 + t] += v.y;
        if (m2 >= 0) sbins[m2*256 + t] += v.z;
        if (m3 >= 0) sbins[m3*256 + t] += v.w;
    }
    #pragma unroll
    for (int m = 0; m < NM; m++)
        g_mfpart[((b*4 + pc)*NM + m)*C2 + c] = sbins[m*256 + t];
}

// -------- K3: count + reduce partials + /(cnt+1e-5) + L2-normalize + copy --------
__global__ void k_mf0(const float* __restrict__ f0, const float* __restrict__ f1,
                      float* __restrict__ out) {
    int bid = blockIdx.x;
    if (bid >= 128) { copy_chunk(f0, f1, out, CPS_MF0 + (long)(bid-128)*1024); return; }
    int b = bid >> 5, m = bid & 31, t = threadIdx.x;   // 256
    __shared__ float red[256];
    const int* ip = g_idx + b*P2;
    int cnt = 0;
    #pragma unroll
    for (int j = 0; j < 4; j++) cnt += (ip[t + j*256] == m);
    red[t] = (float)cnt; __syncthreads();
    for (int s = 128; s > 0; s >>= 1) { if (t < s) red[t] += red[t+s]; __syncthreads(); }
    float inv = 1.f / (red[0] + 1e-5f);
    __syncthreads();
    float r[4]; float sq = 0.f;
    #pragma unroll
    for (int j = 0; j < 4; j++) {
        int c = t + j*256;
        float v = 0.f;
        #pragma unroll
        for (int pc = 0; pc < 4; pc++)
            v += g_mfpart[((b*4 + pc)*NM + m)*C2 + c];
        r[j] = v * inv;
        sq += r[j]*r[j];
    }
    red[t] = sq; __syncthreads();
    for (int s = 128; s > 0; s >>= 1) { if (t < s) red[t] += red[t+s]; __syncthreads(); }
    float scale = 1.f / fmaxf(sqrtf(red[0]), 1e-12f);
    #pragma unroll
    for (int j = 0; j < 4; j++)
        g_mf0[(b*NM + m)*C2 + t + j*256] = r[j]*scale;
}

// -------- K4: q GEMM v3 — all-batch block, 8x8 register tile --------
// own 256 blocks: cb (8 channel-blocks) x ks (32 K-splits). Block covers
// all 128 rows x 128 channels x 32 K. W staged ONCE total across batches.
__global__ void __launch_bounds__(256, 2)
k_qgemm(const float* __restrict__ W, const float* __restrict__ f0,
        const float* __restrict__ f1, float* __restrict__ out) {
    int bid = blockIdx.x;
    if (bid >= 256) { copy_chunk(f0, f1, out, CPS_QG + (long)(bid-256)*1024); return; }
    int cb = bid >> 5, ks = bid & 31;
    int t = threadIdx.x;                       // 256
    __shared__ float sW[KC][128];              // [k][c] 16KB
    __shared__ float sM[KC][128];              // [k][row] 16KB
    #pragma unroll
    for (int it = 0; it < 4; it++) {
        int task = it*256 + t;
        int c = task & 127, k4 = task >> 7;    // k4: 0..7
        float4 w = *(const float4*)(W + ((long)(cb*128 + c))*C2 + ks*KC + k4*4);
        sW[k4*4+0][c] = w.x; sW[k4*4+1][c] = w.y;
        sW[k4*4+2][c] = w.z; sW[k4*4+3][c] = w.w;
        float4 v = *(const float4*)(g_mf0 + (long)c*C2 + ks*KC + k4*4);  // c = row
        sM[k4*4+0][c] = v.x; sM[k4*4+1][c] = v.y;
        sM[k4*4+2][c] = v.z; sM[k4*4+3][c] = v.w;
    }
    __syncthreads();
    int c0 = (t & 15)*8, r0 = (t >> 4)*8;
    float acc[8][8];
    #pragma unroll
    for (int i = 0; i < 8; i++)
        #pragma unroll
        for (int j = 0; j < 8; j++) acc[i][j] = 0.f;
    #pragma unroll 2
    for (int k = 0; k < KC; k++) {
        float4 ca = *(const float4*)&sW[k][c0];
        float4 cb4 = *(const float4*)&sW[k][c0+4];
        float4 ra = *(const float4*)&sM[k][r0];
        float4 rb = *(const float4*)&sM[k][r0+4];
        float cf[8] = {ca.x,ca.y,ca.z,ca.w, cb4.x,cb4.y,cb4.z,cb4.w};
        float rf[8] = {ra.x,ra.y,ra.z,ra.w, rb.x,rb.y,rb.z,rb.w};
        #pragma unroll
        for (int ri = 0; ri < 8; ri++)
            #pragma unroll
            for (int ci = 0; ci < 8; ci++)
                acc[ri][ci] += rf[ri]*cf[ci];
    }
    #pragma unroll
    for (int ri = 0; ri < 8; ri++) {
        long o = ((long)ks*NR + r0 + ri)*C2 + cb*128 + c0;
        *(float4*)(g_qpart + o)     = make_float4(acc[ri][0],acc[ri][1],acc[ri][2],acc[ri][3]);
        *(float4*)(g_qpart + o + 4) = make_float4(acc[ri][4],acc[ri][5],acc[ri][6],acc[ri][7]);
    }
}

// -------- K5: q = sum(K-splits) + bias; row norms + copy --------
__global__ void k_qreduce(const float* __restrict__ bias, const float* __restrict__ f0,
                          const float* __restrict__ f1, float* __restrict__ out) {
    int bid = blockIdx.x;
    if (bid >= 128) { copy_chunk(f0, f1, out, CPS_QR + (long)(bid-128)*1024); return; }
    int row = bid, t = threadIdx.x;   // 256
    float r[4]; float sq = 0.f;
    #pragma unroll
    for (int j = 0; j < 4; j++) {
        int c = t + j*256;
        float v = bias[c];
        #pragma unroll
        for (int ks = 0; ks < KS; ks++)
            v += g_qpart[((long)ks*NR + row)*C2 + c];
        r[j] = v; sq += v*v;
        g_q[(long)row*C2 + c] = v;
    }
    __shared__ float red[256];
    red[t] = sq; __syncthreads();
    for (int s = 128; s > 0; s >>= 1) { if (t < s) red[t] += red[t+s]; __syncthreads(); }
    if (t == 0) g_qn[row] = sqrtf(red[0]);
}

// -------- K6: sim row -> edge row + copy --------
__global__ void k_simedge(const float* __restrict__ f0, const float* __restrict__ f1,
                          float* __restrict__ out) {
    int bid = blockIdx.x;
    if (bid >= 128) { copy_chunk(f0, f1, out, CPS_SE + (long)(bid-128)*1024); return; }
    int b = bid >> 5, i = bid & 31, t = threadIdx.x;   // 256
    int j = t >> 3, s = t & 7;
    const float4* qi = (const float4*)(g_q + (long)(b*NM + i)*C2 + s*128);
    const float4* qj = (const float4*)(g_q + (long)(b*NM + j)*C2 + s*128);
    float part = 0.f;
    #pragma unroll 8
    for (int k = 0; k < 32; k++) {
        float4 a = qi[k], bb = qj[k];
        part += a.x*bb.x + a.y*bb.y + a.z*bb.z + a.w*bb.w;
    }
    __shared__ float sd[NM*8];
    sd[j*8 + s] = part;
    __syncthreads();
    if (t < NM) {
        float d = 0.f;
        #pragma unroll
        for (int ss = 0; ss < 8; ss++) d += sd[t*8 + ss];
        float sim = d / (g_qn[b*NM + i]*g_qn[b*NM + t] + 1e-8f);
        float tot = sim;
        #pragma unroll
        for (int o = 16; o; o >>= 1) tot += __shfl_xor_sync(0xffffffffu, tot, o);
        g_edge[(b*NM + i)*NM + t] = sim / (tot + 1e-8f);
    }
}

// -------- K7: gp = edge @ q; deterministic block-partial sq-norms + copy --------
__global__ void k_gp(const float* __restrict__ f0, const float* __restrict__ f1,
                     float* __restrict__ out) {
    int bid = blockIdx.x;
    if (bid >= 16) { copy_chunk(f0, f1, out, CPS_GP + (long)(bid-16)*1024); return; }
    int b = bid >> 2, ct = bid & 3, t = threadIdx.x;  // 256
    int c = ct*256 + t;
    __shared__ float se[NM*NM];
    for (int i = t; i < NM*NM; i += 256) se[i] = g_edge[b*NM*NM + i];
    __syncthreads();
    float acc[NM];
    #pragma unroll
    for (int m = 0; m < NM; m++) acc[m] = 0.f;
    #pragma unroll 4
    for (int n = 0; n < NM; n++) {
        float qv = g_q[(long)(b*NM + n)*C2 + c];
        #pragma unroll
        for (int m = 0; m < NM; m++) acc[m] += se[m*NM + n]*qv;
    }
    __shared__ float sw[NM*8];
    int w = t >> 5, l = t & 31;
    #pragma unroll
    for (int m = 0; m < NM; m++) {
        g_gp[(long)(b*NM + m)*C2 + c] = acc[m];
        float v = acc[m]*acc[m];
        #pragma unroll
        for (int o = 16; o; o >>= 1) v += __shfl_xor_sync(0xffffffffu, v, o);
        if (l == 0) sw[m*8 + w] = v;
    }
    __syncthreads();
    if (t < NM) {
        float s2 = 0.f;
        #pragma unroll
        for (int ww = 0; ww < 8; ww++) s2 += sw[t*8 + ww];
        g_gpsqp[(b*4 + ct)*NM + t] = s2;
    }
}

// -------- K8: per-(b,m) gate scale + copy --------
__global__ void k_scale(const float* __restrict__ gate, const float* __restrict__ f0,
                        const float* __restrict__ f1, float* __restrict__ out) {
    int bid = blockIdx.x;
    if (bid >= 1) { copy_chunk(f0, f1, out, CPS_SC + (long)(bid-1)*1024); return; }
    int i = threadIdx.x;                 // 128 = NB*NM live lanes
    if (i < NB*NM) {
        int b = i >> 5, m = i & 31;
        float s2 = 0.f;
        #pragma unroll
        for (int ct = 0; ct < 4; ct++) s2 += g_gpsqp[(b*4 + ct)*NM + m];
        float sg = 1.f / (1.f + expf(-gate[0]));
        g_scale[i] = sg / fmaxf(sqrtf(s2), 1e-12f);
    }
}

// -------- K9: out2 = feat2 + gather(mf_final) --------
__global__ void k_final2(const float* __restrict__ f2, float* __restrict__ out) {
    long base = (long)blockIdx.x*1024;
    #pragma unroll
    for (int j = 0; j < 4; j++) {
        long o4 = base + j*256 + threadIdx.x;           // < 2^20
        int b   = (int)(o4 >> 18);                      // 262144 float4/batch
        int rem = (int)(o4 & 262143);
        int c   = rem >> 8;
        int p   = (rem & 255)*4;
        float4 v = ((const float4*)f2)[o4];
        int4 mm = *(const int4*)(g_idx + b*P2 + p);
        float* vv = (float*)&v;
        int mmv[4] = {mm.x, mm.y, mm.z, mm.w};
        #pragma unroll
        for (int q = 0; q < 4; q++) {
            int m = mmv[q];
            if (m >= 0) {
                long a = (long)(b*NM + m)*C2 + c;
                vv[q] += g_mf0[a] + g_scale[b*NM + m]*g_gp[a];
            }
        }
        ((float4*)out)[(OFF2/4) + o4] = v;
    }
}

extern "C" void kernel_launch(void* const* d_in, const int* in_sizes, int n_in,
                              void* d_out, int out_size) {
    // Resolve inputs by unique element counts (robust to metadata ordering).
    const float* f0 = 0; const float* f1 = 0; const float* f2 = 0;
    const int* sam = 0; const float* W2 = 0; const float* b2 = 0;
    const float* g2 = 0;
    for (int i = 0; i < n_in; i++) {
        switch (in_sizes[i]) {
            case 16777216: f0  = (const float*)d_in[i]; break;  // 4*256*128*128
            case 8388608:  f1  = (const float*)d_in[i]; break;  // 4*512*64*64
            case 4194304:  f2  = (const float*)d_in[i]; break;  // 4*1024*32*32
            case 34603008: sam = (const int*)d_in[i];   break;  // 4*33*512*512
            case 1048576:  W2  = (const float*)d_in[i]; break;  // 1024*1024
            case 1024:     b2  = (const float*)d_in[i]; break;  // bias2
            case 1: if (!g2) g2 = (const float*)d_in[i]; break; // gates all equal
            default: break;
        }
    }
    float* out = (float*)d_out;

    k_idx    <<<128 + CPN_IDX, 1024>>>(sam, f0, f1, out);
    k_mfpart <<<64  + CPN_MFP, 256>>>(f2, f0, f1, out);
    k_mf0    <<<128 + CPN_MF0, 256>>>(f0, f1, out);
    k_qgemm  <<<256 + CPN_QG,  256>>>(W2, f0, f1, out);
    k_qreduce<<<128 + CPN_QR,  256>>>(b2, f0, f1, out);
    k_simedge<<<128 + CPN_SE,  256>>>(f0, f1, out);
    k_gp     <<<16  + CPN_GP,  256>>>(f0, f1, out);
    k_scale  <<<1   + CPN_SC,  256>>>(g2, f0, f1, out);
    k_final2 <<<1024, 256>>>(f2, out);
}